// round 6
// baseline (speedup 1.0000x reference)
#include <cuda_runtime.h>
#include <cuda_bf16.h>
#include <math.h>

#define N 512
#define D 512
#define MARGIN 0.3f
#define EPSF 1e-12f

#define BM 64
#define BN 64
#define BK 16
#define NBLK 64           // (N/BM)*(N/BN) = 8*8
#define ANCH_PER_BLK (N / NBLK)   // 8

// Scratch (no cudaMalloc allowed)
__device__ float g_dist[N * N];
__device__ float g_partial_loss[NBLK];
__device__ long long g_partial_cnt[NBLK];
__device__ int g_bar_count = 0;
__device__ volatile int g_bar_gen = 0;
__device__ int g_done = 0;

__global__ __launch_bounds__(256) void fused_kernel(const float* __restrict__ A,
                                                    const int* __restrict__ targets,
                                                    float* __restrict__ out) {
    __shared__ float As[BK][BM + 4];
    __shared__ float Bs[BK][BN + 4];
    __shared__ float sqA[BM];
    __shared__ float sqB[BN];

    int tid = threadIdx.x;
    int bx = blockIdx.x & 7;    // tile col
    int by = blockIdx.x >> 3;   // tile row
    int tx = tid & 15;
    int ty = tid >> 4;
    int m0 = by * BM;
    int n0 = bx * BN;

    // ------------------- Phase 1: distance tile -------------------
    int lrow = tid >> 2;
    int lk4  = (tid & 3) * 4;

    float acc[4][4] = {};
    float psqA = 0.f, psqB = 0.f;

    for (int k0 = 0; k0 < D; k0 += BK) {
        float4 av = *(const float4*)&A[(m0 + lrow) * D + k0 + lk4];
        float4 bv = *(const float4*)&A[(n0 + lrow) * D + k0 + lk4];
        psqA += av.x * av.x + av.y * av.y + av.z * av.z + av.w * av.w;
        psqB += bv.x * bv.x + bv.y * bv.y + bv.z * bv.z + bv.w * bv.w;
        As[lk4 + 0][lrow] = av.x;
        As[lk4 + 1][lrow] = av.y;
        As[lk4 + 2][lrow] = av.z;
        As[lk4 + 3][lrow] = av.w;
        Bs[lk4 + 0][lrow] = bv.x;
        Bs[lk4 + 1][lrow] = bv.y;
        Bs[lk4 + 2][lrow] = bv.z;
        Bs[lk4 + 3][lrow] = bv.w;
        __syncthreads();
#pragma unroll
        for (int k = 0; k < BK; k++) {
            float4 a4 = *(const float4*)&As[k][ty * 4];
            float4 b4 = *(const float4*)&Bs[k][tx * 4];
            float a[4] = {a4.x, a4.y, a4.z, a4.w};
            float b[4] = {b4.x, b4.y, b4.z, b4.w};
#pragma unroll
            for (int i = 0; i < 4; i++)
#pragma unroll
                for (int j = 0; j < 4; j++)
                    acc[i][j] = fmaf(a[i], b[j], acc[i][j]);
        }
        __syncthreads();
    }

    // Row-norm reduction across the 4 threads sharing each row.
    psqA += __shfl_xor_sync(0xffffffffu, psqA, 1);
    psqA += __shfl_xor_sync(0xffffffffu, psqA, 2);
    psqB += __shfl_xor_sync(0xffffffffu, psqB, 1);
    psqB += __shfl_xor_sync(0xffffffffu, psqB, 2);
    if ((tid & 3) == 0) {
        sqA[lrow] = psqA;
        sqB[lrow] = psqB;
    }
    __syncthreads();

    int colb = n0 + tx * 4;
    float sc0 = sqB[tx * 4 + 0], sc1 = sqB[tx * 4 + 1];
    float sc2 = sqB[tx * 4 + 2], sc3 = sqB[tx * 4 + 3];
#pragma unroll
    for (int i = 0; i < 4; i++) {
        int row = m0 + ty * 4 + i;
        float sr = sqA[ty * 4 + i];
        float4 o;
        o.x = sqrtf(fmaxf(sr + sc0 - 2.f * acc[i][0], EPSF));
        o.y = sqrtf(fmaxf(sr + sc1 - 2.f * acc[i][1], EPSF));
        o.z = sqrtf(fmaxf(sr + sc2 - 2.f * acc[i][2], EPSF));
        o.w = sqrtf(fmaxf(sr + sc3 - 2.f * acc[i][3], EPSF));
        *(float4*)&g_dist[row * N + colb] = o;
    }

    // ------------------- Grid barrier (64 co-resident blocks) -------------------
    __syncthreads();
    if (tid == 0) {
        int gen = g_bar_gen;
        __threadfence();   // make g_dist writes visible before arrival
        if (atomicAdd(&g_bar_count, 1) == NBLK - 1) {
            g_bar_count = 0;        // safe: all arrived, no concurrent atomics
            __threadfence();
            g_bar_gen = gen + 1;    // monotonic generation -> graph-replay safe
        } else {
            while (g_bar_gen == gen) { }
        }
        __threadfence();
    }
    __syncthreads();

    // ------------------- Phase 2: 8 anchors per block -------------------
    __shared__ float drow[N];
    __shared__ float posv[N];
    __shared__ int   tgt_sh[N];
    __shared__ int   npos_sh;
    __shared__ float ws[8];
    __shared__ int   is_last_sh;

    for (int j = tid; j < N; j += 256) tgt_sh[j] = targets[j];
    __syncthreads();

    float blk_loss = 0.f;       // thread 0 accumulates across anchors
    long long blk_cnt = 0;

    for (int a = 0; a < ANCH_PER_BLK; a++) {
        int i = blockIdx.x * ANCH_PER_BLK + a;

        if (tid == 0) npos_sh = 0;
        for (int j = tid; j < N; j += 256) drow[j] = g_dist[i * N + j];
        __syncthreads();

        int ti = tgt_sh[i];
        for (int j = tid; j < N; j += 256) {
            if (tgt_sh[j] == ti) {
                int p = atomicAdd(&npos_sh, 1);
                posv[p] = drow[j];
            }
        }
        __syncthreads();
        int np = npos_sh;
        int nn = N - np;

        float sum = 0.f;
        for (int j = tid; j < N; j += 256) {
            if (tgt_sh[j] != ti) {
                float base = MARGIN - drow[j];
                for (int p = 0; p < np; p++) {
                    sum += fmaxf(posv[p] + base, 0.f);
                }
            }
        }
        for (int o = 16; o > 0; o >>= 1) sum += __shfl_down_sync(0xffffffffu, sum, o);
        if ((tid & 31) == 0) ws[tid >> 5] = sum;
        __syncthreads();
        if (tid == 0) {
            float t = 0.f;
#pragma unroll
            for (int w = 0; w < 8; w++) t += ws[w];
            blk_loss += t;
            blk_cnt += (long long)np * nn;
        }
        __syncthreads();
    }

    // ------------------- Final reduction (last block done) -------------------
    if (tid == 0) {
        g_partial_loss[blockIdx.x] = blk_loss;
        g_partial_cnt[blockIdx.x]  = blk_cnt;
        __threadfence();
        int prev = atomicAdd(&g_done, 1);
        is_last_sh = (prev == NBLK - 1);
    }
    __syncthreads();

    if (is_last_sh && tid == 0) {
        float ts = 0.f;
        long long tc = 0;
#pragma unroll
        for (int b = 0; b < NBLK; b++) {
            ts += g_partial_loss[b];
            tc += g_partial_cnt[b];
        }
        out[0] = ts / (float)tc;
        g_done = 0;   // reset for next graph replay
    }
}

extern "C" void kernel_launch(void* const* d_in, const int* in_sizes, int n_in,
                              void* d_out, int out_size) {
    const float* A       = (const float*)d_in[0];
    const int*   targets = (const int*)d_in[1];
    float*       out     = (float*)d_out;

    fused_kernel<<<NBLK, 256>>>(A, targets, out);
}